// round 12
// baseline (speedup 1.0000x reference)
#include <cuda_runtime.h>
#include <cuda_pipeline.h>
#include <cuda_fp16.h>
#include <mma.h>
#include <math.h>

using namespace nvcuda;

#define T_   64
#define B_   256
#define NIN_ 1024
#define H_   2048
#define G_   8192   // 4*H
#define NSPLIT 2    // split-K factor for recurrent GEMM
#define BHALF 128   // batch rows per stream
#define NCHUNK 8    // xw GEMM time-chunks
#define TCHUNK (T_ / NCHUNK)

// ---- scratch ----
__device__ float g_A[(size_t)T_ * B_ * G_];
__device__ float g_HWp[(size_t)NSPLIT * B_ * G_];
__device__ float g_c[(size_t)B_ * H_];
__device__ __half g_hh[(size_t)B_ * H_];
__device__ __half g_hl[(size_t)B_ * H_];
__device__ __half g_xh[(size_t)T_ * B_ * NIN_];
__device__ __half g_xl[(size_t)T_ * B_ * NIN_];
__device__ __half g_wxh[(size_t)NIN_ * G_];
__device__ __half g_wxl[(size_t)NIN_ * G_];
__device__ __half g_whh[(size_t)H_ * G_];
__device__ __half g_whl[(size_t)H_ * G_];

// ============================================================
// fp16x3 tensor-core GEMM, pre-split operands.
// C[M,N](fp32) = A[M,K] @ B[K,N];  acc = ah*bh + ah*bl + al*bh.
// Block 128x128, 8 warps (4x2), warp tile 32x64.
// BK=32, 3-stage cp.async, one __syncthreads per k-iter.
// blockIdx.z = split-K index (output C + z*zstride).
// ============================================================
#define GBM 128
#define GBN 128
#define GBK 32
#define ALD 40
#define BLD 136
#define NSTAGE 3
#define AS_H (GBM * ALD)
#define BS_H (GBK * BLD)
#define STAGE_H (2 * AS_H + 2 * BS_H)
#define SMEM_BYTES (STAGE_H * NSTAGE * 2)

__global__ __launch_bounds__(256, 2) void fp16x3_gemm(
    const __half* __restrict__ Ahi, const __half* __restrict__ Alo,
    const __half* __restrict__ Bhi, const __half* __restrict__ Blo,
    float* __restrict__ C, long long zstride, int N, int K, int K_chunk)
{
    extern __shared__ __half smem[];

    const int tid = threadIdx.x;
    const int z = blockIdx.z;
    const int kstart = z * K_chunk;

    const size_t aoff = (size_t)blockIdx.y * GBM * K + kstart;
    const size_t boff = (size_t)kstart * N + (size_t)blockIdx.x * GBN;
    const __half* Abh = Ahi + aoff;
    const __half* Abl = Alo + aoff;
    const __half* Bbh = Bhi + boff;
    const __half* Bbl = Blo + boff;

    const int warp = tid >> 5;
    const int wm = warp & 3;
    const int wn = warp >> 2;

    const int NIT = K_chunk / GBK;

    wmma::fragment<wmma::accumulator, 16, 16, 16, float> acc[2][4];
    #pragma unroll
    for (int i = 0; i < 2; i++)
        #pragma unroll
        for (int j = 0; j < 4; j++)
            wmma::fill_fragment(acc[i][j], 0.0f);

    auto prefetch = [&](int it) {
        __half* s = smem + (size_t)(it % NSTAGE) * STAGE_H;
        __half* sAh = s;
        __half* sAl = s + AS_H;
        __half* sBh = s + 2 * AS_H;
        __half* sBl = s + 2 * AS_H + BS_H;
        const int k0 = it * GBK;
        #pragma unroll
        for (int q = 0; q < 2; q++) {
            int sa = tid * 2 + q;
            int r = sa >> 2, c = (sa & 3) * 8;
            __pipeline_memcpy_async(&sAh[r * ALD + c], Abh + (size_t)r * K + k0 + c, 16);
            __pipeline_memcpy_async(&sAl[r * ALD + c], Abl + (size_t)r * K + k0 + c, 16);
            int rb = sa >> 4, cb = (sa & 15) * 8;
            __pipeline_memcpy_async(&sBh[rb * BLD + cb], Bbh + (size_t)(k0 + rb) * N + cb, 16);
            __pipeline_memcpy_async(&sBl[rb * BLD + cb], Bbl + (size_t)(k0 + rb) * N + cb, 16);
        }
    };

    prefetch(0); __pipeline_commit();
    if (NIT > 1) { prefetch(1); __pipeline_commit(); }

    for (int it = 0; it < NIT; ++it) {
        __pipeline_wait_prior((it + 1 < NIT) ? 1 : 0);
        __syncthreads();

        if (it + 2 < NIT) { prefetch(it + 2); __pipeline_commit(); }

        const __half* s = smem + (size_t)(it % NSTAGE) * STAGE_H;
        const __half* sAh = s;
        const __half* sAl = s + AS_H;
        const __half* sBh = s + 2 * AS_H;
        const __half* sBl = s + 2 * AS_H + BS_H;

        #pragma unroll
        for (int ks = 0; ks < GBK; ks += 16) {
            wmma::fragment<wmma::matrix_a, 16, 16, 16, __half, wmma::row_major> ah[2], al[2];
            #pragma unroll
            for (int i = 0; i < 2; i++) {
                wmma::load_matrix_sync(ah[i], &sAh[(wm * 32 + i * 16) * ALD + ks], ALD);
                wmma::load_matrix_sync(al[i], &sAl[(wm * 32 + i * 16) * ALD + ks], ALD);
            }
            #pragma unroll
            for (int j = 0; j < 4; j++) {
                const int colb = wn * 64 + j * 16;
                wmma::fragment<wmma::matrix_b, 16, 16, 16, __half, wmma::row_major> bf;
                wmma::load_matrix_sync(bf, &sBh[ks * BLD + colb], BLD);
                wmma::mma_sync(acc[0][j], al[0], bf, acc[0][j]);
                wmma::mma_sync(acc[1][j], al[1], bf, acc[1][j]);
                wmma::mma_sync(acc[0][j], ah[0], bf, acc[0][j]);
                wmma::mma_sync(acc[1][j], ah[1], bf, acc[1][j]);
                wmma::load_matrix_sync(bf, &sBl[ks * BLD + colb], BLD);
                wmma::mma_sync(acc[0][j], ah[0], bf, acc[0][j]);
                wmma::mma_sync(acc[1][j], ah[1], bf, acc[1][j]);
            }
        }
    }

    float* Cb = C + (size_t)z * zstride
                  + (size_t)(blockIdx.y * GBM + wm * 32) * N
                  + (size_t)blockIdx.x * GBN + wn * 64;
    #pragma unroll
    for (int i = 0; i < 2; i++)
        #pragma unroll
        for (int j = 0; j < 4; j++)
            wmma::store_matrix_sync(Cb + (size_t)(i * 16) * N + j * 16,
                                    acc[i][j], N, wmma::mem_row_major);
}

// ============================================================
__device__ __forceinline__ float fsigmoid(float x)
{
    return __fdividef(1.f, 1.f + __expf(-x));
}
__device__ __forceinline__ float ftanh(float x)
{
    return __fdividef(2.f, 1.f + __expf(-2.f * x)) - 1.f;
}

__global__ void split_kernel(const float* __restrict__ in,
                             __half* __restrict__ hi, __half* __restrict__ lo,
                             int n)
{
    int i = blockIdx.x * blockDim.x + threadIdx.x;
    if (i < n) {
        float v = in[i];
        __half h = __float2half_rn(v);
        hi[i] = h;
        lo[i] = __float2half_rn(v - __half2float(h));
    }
}

__device__ __forceinline__ void blk_reduce2_512(float& s, float& s2)
{
    __shared__ float rbuf[2][16];
    const int lane = threadIdx.x & 31;
    const int warp = threadIdx.x >> 5;
    #pragma unroll
    for (int o = 16; o; o >>= 1) {
        s  += __shfl_down_sync(0xffffffffu, s,  o);
        s2 += __shfl_down_sync(0xffffffffu, s2, o);
    }
    if (lane == 0) { rbuf[0][warp] = s; rbuf[1][warp] = s2; }
    __syncthreads();
    if (warp == 0) {
        s  = (lane < 16) ? rbuf[0][lane] : 0.f;
        s2 = (lane < 16) ? rbuf[1][lane] : 0.f;
        #pragma unroll
        for (int o = 8; o; o >>= 1) {
            s  += __shfl_down_sync(0xffffffffu, s,  o);
            s2 += __shfl_down_sync(0xffffffffu, s2, o);
        }
        if (lane == 0) { rbuf[0][0] = s; rbuf[1][0] = s2; }
    }
    __syncthreads();
    s  = rbuf[0][0];
    s2 = rbuf[1][0];
    __syncthreads();
}

__device__ __forceinline__ void blk_reduce2(float& s, float& s2)
{
    __shared__ float rbuf[2][8];
    const int lane = threadIdx.x & 31;
    const int warp = threadIdx.x >> 5;
    #pragma unroll
    for (int o = 16; o; o >>= 1) {
        s  += __shfl_down_sync(0xffffffffu, s,  o);
        s2 += __shfl_down_sync(0xffffffffu, s2, o);
    }
    if (lane == 0) { rbuf[0][warp] = s; rbuf[1][warp] = s2; }
    __syncthreads();
    if (warp == 0) {
        s  = (lane < 8) ? rbuf[0][lane] : 0.f;
        s2 = (lane < 8) ? rbuf[1][lane] : 0.f;
        #pragma unroll
        for (int o = 4; o; o >>= 1) {
            s  += __shfl_down_sync(0xffffffffu, s,  o);
            s2 += __shfl_down_sync(0xffffffffu, s2, o);
        }
        if (lane == 0) { rbuf[0][0] = s; rbuf[1][0] = s2; }
    }
    __syncthreads();
    s  = rbuf[0][0];
    s2 = rbuf[1][0];
    __syncthreads();
}

__global__ __launch_bounds__(256) void ln_rows_add_kernel(
    const float* __restrict__ Cin, const float* __restrict__ gamma,
    const float* __restrict__ beta, const float* __restrict__ bias,
    float* __restrict__ Aout)
{
    const int row = blockIdx.x;
    const float* x = Cin + (size_t)row * G_;
    float s = 0.f, s2 = 0.f;
    for (int j = threadIdx.x; j < G_; j += 256) {
        float v = x[j]; s += v; s2 += v * v;
    }
    blk_reduce2(s, s2);
    const float inv = 1.f / (float)G_;
    float mu   = s * inv;
    float rstd = rsqrtf(s2 * inv - mu * mu + 1e-5f);
    float* o = Aout + (size_t)row * G_;
    for (int j = threadIdx.x; j < G_; j += 256) {
        o[j] = (x[j] - mu) * rstd * gamma[j] + beta[j] + bias[j];
    }
}

__global__ void init_state_kernel(const float* __restrict__ init,
                                  const float* __restrict__ mask)
{
    int idx = blockIdx.x * blockDim.x + threadIdx.x;
    int b = idx >> 11;
    int j = idx & (H_ - 1);
    size_t base = (size_t)b * T_ * 2 * H_;
    g_c[idx] = init[base + j];
    float h = init[base + H_ + j] * (1.f - mask[b]);
    __half hh = __float2half_rn(h);
    g_hh[idx] = hh;
    g_hl[idx] = __float2half_rn(h - __half2float(hh));
}

// ============================================================
// Fused cell for one batch half (grid = BHALF blocks, 512 thr).
// ============================================================
__global__ __launch_bounds__(512) void cell_kernel(
    int t, int b0, const float* __restrict__ mask,
    const float* __restrict__ A,
    const float* __restrict__ gh, const float* __restrict__ bh,
    const float* __restrict__ gc, const float* __restrict__ bc,
    float* __restrict__ hs)
{
    const int b = blockIdx.x + b0;
    const int tid = threadIdx.x;
    const float keep = 1.f - mask[t * B_ + b];
    const float keep_next = (t + 1 < T_) ? (1.f - mask[(t + 1) * B_ + b]) : 1.f;
    const float* hw0 = g_HWp + (size_t)b * G_;
    const size_t PS = (size_t)B_ * G_;
    const float* a = A + ((size_t)t * B_ + b) * G_;

    float s = 0.f, s2 = 0.f;
    #pragma unroll
    for (int p = 0; p < G_ / (512 * 4); p++) {
        int i4 = (tid + p * 512) * 4;
        float4 p0 = *(const float4*)(hw0 + i4);
        float4 p1 = *(const float4*)(hw0 + PS + i4);
        float v0 = p0.x + p1.x, v1 = p0.y + p1.y;
        float v2 = p0.z + p1.z, v3 = p0.w + p1.w;
        s  += v0 + v1 + v2 + v3;
        s2 += v0 * v0 + v1 * v1 + v2 * v2 + v3 * v3;
    }
    blk_reduce2_512(s, s2);
    const float invG = 1.f / (float)G_;
    float mu   = s * invG;
    float rstd = rsqrtf(s2 * invG - mu * mu + 1e-5f);

    const int j0 = tid * 4;
    float cs = 0.f, cs2 = 0.f;
    float cn4[4], og4[4];
    {
        float4 hwi = *(const float4*)(hw0 + j0);
        float4 hwf = *(const float4*)(hw0 + H_ + j0);
        float4 hwo = *(const float4*)(hw0 + 2 * H_ + j0);
        float4 hwu = *(const float4*)(hw0 + 3 * H_ + j0);
        float4 q;
        q = *(const float4*)(hw0 + PS + j0);            hwi.x += q.x; hwi.y += q.y; hwi.z += q.z; hwi.w += q.w;
        q = *(const float4*)(hw0 + PS + H_ + j0);       hwf.x += q.x; hwf.y += q.y; hwf.z += q.z; hwf.w += q.w;
        q = *(const float4*)(hw0 + PS + 2 * H_ + j0);   hwo.x += q.x; hwo.y += q.y; hwo.z += q.z; hwo.w += q.w;
        q = *(const float4*)(hw0 + PS + 3 * H_ + j0);   hwu.x += q.x; hwu.y += q.y; hwu.z += q.z; hwu.w += q.w;

        float4 ai = *(const float4*)(a + j0);
        float4 af = *(const float4*)(a + H_ + j0);
        float4 ao = *(const float4*)(a + 2 * H_ + j0);
        float4 au = *(const float4*)(a + 3 * H_ + j0);
        float4 ghi = *(const float4*)(gh + j0);
        float4 ghf = *(const float4*)(gh + H_ + j0);
        float4 gho = *(const float4*)(gh + 2 * H_ + j0);
        float4 ghu = *(const float4*)(gh + 3 * H_ + j0);
        float4 bhi = *(const float4*)(bh + j0);
        float4 bhf = *(const float4*)(bh + H_ + j0);
        float4 bho = *(const float4*)(bh + 2 * H_ + j0);
        float4 bhu = *(const float4*)(bh + 3 * H_ + j0);
        float4 cc  = *(const float4*)(&g_c[(size_t)b * H_ + j0]);

        float hwi_[4] = {hwi.x, hwi.y, hwi.z, hwi.w};
        float hwf_[4] = {hwf.x, hwf.y, hwf.z, hwf.w};
        float hwo_[4] = {hwo.x, hwo.y, hwo.z, hwo.w};
        float hwu_[4] = {hwu.x, hwu.y, hwu.z, hwu.w};
        float ai_[4]  = {ai.x, ai.y, ai.z, ai.w};
        float af_[4]  = {af.x, af.y, af.z, af.w};
        float ao_[4]  = {ao.x, ao.y, ao.z, ao.w};
        float au_[4]  = {au.x, au.y, au.z, au.w};
        float ghi_[4] = {ghi.x, ghi.y, ghi.z, ghi.w};
        float ghf_[4] = {ghf.x, ghf.y, ghf.z, ghf.w};
        float gho_[4] = {gho.x, gho.y, gho.z, gho.w};
        float ghu_[4] = {ghu.x, ghu.y, ghu.z, ghu.w};
        float bhi_[4] = {bhi.x, bhi.y, bhi.z, bhi.w};
        float bhf_[4] = {bhf.x, bhf.y, bhf.z, bhf.w};
        float bho_[4] = {bho.x, bho.y, bho.z, bho.w};
        float bhu_[4] = {bhu.x, bhu.y, bhu.z, bhu.w};
        float cc_[4]  = {cc.x, cc.y, cc.z, cc.w};

        #pragma unroll
        for (int q4 = 0; q4 < 4; q4++) {
            float zi = ai_[q4] + (hwi_[q4] - mu) * rstd * ghi_[q4] + bhi_[q4];
            float zf = af_[q4] + (hwf_[q4] - mu) * rstd * ghf_[q4] + bhf_[q4];
            float zo = ao_[q4] + (hwo_[q4] - mu) * rstd * gho_[q4] + bho_[q4];
            float zu = au_[q4] + (hwu_[q4] - mu) * rstd * ghu_[q4] + bhu_[q4];
            float ig = fsigmoid(zi);
            float fg = fsigmoid(zf);
            float og = fsigmoid(zo);
            float ug = ftanh(zu);
            float cn = fg * (cc_[q4] * keep) + ig * ug;
            cn4[q4] = cn;
            og4[q4] = og;
            cs += cn; cs2 += cn * cn;
        }
        *(float4*)(&g_c[(size_t)b * H_ + j0]) =
            make_float4(cn4[0], cn4[1], cn4[2], cn4[3]);
    }
    blk_reduce2_512(cs, cs2);
    const float invH = 1.f / (float)H_;
    float muc   = cs * invH;
    float rstdc = rsqrtf(cs2 * invH - muc * muc + 1e-5f);

    {
        float4 gc4 = *(const float4*)(gc + j0);
        float4 bc4 = *(const float4*)(bc + j0);
        float gc_[4] = {gc4.x, gc4.y, gc4.z, gc4.w};
        float bc_[4] = {bc4.x, bc4.y, bc4.z, bc4.w};
        float hn[4];
        __half hhp[4], hlp[4];
        #pragma unroll
        for (int q4 = 0; q4 < 4; q4++) {
            float v = og4[q4] * ftanh((cn4[q4] - muc) * rstdc * gc_[q4] + bc_[q4]);
            hn[q4] = v;
            float hm = v * keep_next;
            __half hhi = __float2half_rn(hm);
            hhp[q4] = hhi;
            hlp[q4] = __float2half_rn(hm - __half2float(hhi));
        }
        *(float4*)(hs + ((size_t)t * B_ + b) * H_ + j0) =
            make_float4(hn[0], hn[1], hn[2], hn[3]);
        __half2* ph = (__half2*)(&g_hh[(size_t)b * H_ + j0]);
        ph[0] = __halves2half2(hhp[0], hhp[1]);
        ph[1] = __halves2half2(hhp[2], hhp[3]);
        __half2* pl = (__half2*)(&g_hl[(size_t)b * H_ + j0]);
        pl[0] = __halves2half2(hlp[0], hlp[1]);
        pl[1] = __halves2half2(hlp[2], hlp[3]);
    }
}

__global__ void write_state_kernel(const float* __restrict__ hs,
                                   float* __restrict__ sout)
{
    int idx = blockIdx.x * blockDim.x + threadIdx.x;
    int b = idx >> 11;
    int j = idx & (H_ - 1);
    sout[(size_t)b * 2 * H_ + j] = g_c[idx];
    sout[(size_t)b * 2 * H_ + H_ + j] =
        hs[((size_t)(T_ - 1) * B_ + b) * H_ + j];
}

// ============================================================
extern "C" void kernel_launch(void* const* d_in, const int* in_sizes, int n_in,
                              void* d_out, int out_size)
{
    const float* x    = (const float*)d_in[0];
    const float* mask = (const float*)d_in[1];
    const float* init = (const float*)d_in[2];
    const float* wx   = (const float*)d_in[3];
    const float* wh   = (const float*)d_in[4];
    const float* bvec = (const float*)d_in[5];
    const float* gx   = (const float*)d_in[6];
    const float* bx   = (const float*)d_in[7];
    const float* gh   = (const float*)d_in[8];
    const float* bh   = (const float*)d_in[9];
    const float* gc   = (const float*)d_in[10];
    const float* bc   = (const float*)d_in[11];

    float* out  = (float*)d_out;
    float* hs   = out;
    float* sout = out + (size_t)T_ * B_ * H_;

    float *Abuf, *HWp;
    __half *xh, *xl, *wxh, *wxl, *whh, *whl, *hh, *hl;
    cudaGetSymbolAddress((void**)&Abuf, g_A);
    cudaGetSymbolAddress((void**)&HWp,  g_HWp);
    cudaGetSymbolAddress((void**)&xh,   g_xh);
    cudaGetSymbolAddress((void**)&xl,   g_xl);
    cudaGetSymbolAddress((void**)&wxh,  g_wxh);
    cudaGetSymbolAddress((void**)&wxl,  g_wxl);
    cudaGetSymbolAddress((void**)&whh,  g_whh);
    cudaGetSymbolAddress((void**)&whl,  g_whl);
    cudaGetSymbolAddress((void**)&hh,   g_hh);
    cudaGetSymbolAddress((void**)&hl,   g_hl);

    cudaFuncSetAttribute(fp16x3_gemm,
                         cudaFuncAttributeMaxDynamicSharedMemorySize, SMEM_BYTES);

    // prologue on the (captured) default stream
    {
        int nx = T_ * B_ * NIN_;
        split_kernel<<<(nx + 255) / 256, 256>>>(x, xh, xl, nx);
        int nwx = NIN_ * G_;
        split_kernel<<<(nwx + 255) / 256, 256>>>(wx, wxh, wxl, nwx);
        int nwh = H_ * G_;
        split_kernel<<<(nwh + 255) / 256, 256>>>(wh, whh, whl, nwh);
    }
    init_state_kernel<<<(B_ * H_) / 256, 256>>>(init, mask);

    // fork: two batch-half recurrence streams + one xw-producer stream
    cudaStream_t s1, s2, s3;
    cudaStreamCreateWithFlags(&s1, cudaStreamNonBlocking);
    cudaStreamCreateWithFlags(&s2, cudaStreamNonBlocking);
    cudaStreamCreateWithFlags(&s3, cudaStreamNonBlocking);
    cudaEvent_t ev0, ev1, ev2;
    cudaEventCreateWithFlags(&ev0, cudaEventDisableTiming);
    cudaEventCreateWithFlags(&ev1, cudaEventDisableTiming);
    cudaEventCreateWithFlags(&ev2, cudaEventDisableTiming);
    cudaEvent_t evA[NCHUNK];
    for (int c = 0; c < NCHUNK; c++)
        cudaEventCreateWithFlags(&evA[c], cudaEventDisableTiming);

    cudaEventRecord(ev0, 0);
    cudaStreamWaitEvent(s1, ev0, 0);
    cudaStreamWaitEvent(s2, ev0, 0);
    cudaStreamWaitEvent(s3, ev0, 0);

    // xw GEMM + LN in time-chunks on s3 (A[t] ready per chunk)
    const int MCH = TCHUNK * B_;   // rows per chunk = 2048
    for (int c = 0; c < NCHUNK; c++) {
        const __half* xch = xh + (size_t)c * MCH * NIN_;
        const __half* xcl = xl + (size_t)c * MCH * NIN_;
        float* Ach = Abuf + (size_t)c * MCH * G_;
        fp16x3_gemm<<<dim3(G_ / GBN, MCH / GBM, 1), 256, SMEM_BYTES, s3>>>(
            xch, xcl, wxh, wxl, Ach, 0, G_, NIN_, NIN_);
        ln_rows_add_kernel<<<MCH, 256, 0, s3>>>(Ach, gx, bx, bvec, Ach);
        cudaEventRecord(evA[c], s3);
    }

    const int KCH = H_ / NSPLIT;
    const long long ZST = (long long)B_ * G_;

    for (int t = 0; t < T_; t++) {
        if (t % TCHUNK == 0) {
            cudaStreamWaitEvent(s1, evA[t / TCHUNK], 0);
            cudaStreamWaitEvent(s2, evA[t / TCHUNK], 0);
        }
        fp16x3_gemm<<<dim3(G_ / GBN, BHALF / GBM, NSPLIT), 256, SMEM_BYTES, s1>>>(
            hh, hl, whh, whl, HWp, ZST, G_, H_, KCH);
        cell_kernel<<<BHALF, 512, 0, s1>>>(t, 0, mask, Abuf, gh, bh, gc, bc, hs);
        fp16x3_gemm<<<dim3(G_ / GBN, BHALF / GBM, NSPLIT), 256, SMEM_BYTES, s2>>>(
            hh + (size_t)BHALF * H_, hl + (size_t)BHALF * H_, whh, whl,
            HWp + (size_t)BHALF * G_, ZST, G_, H_, KCH);
        cell_kernel<<<BHALF, 512, 0, s2>>>(t, BHALF, mask, Abuf, gh, bh, gc, bc, hs);
    }

    cudaEventRecord(ev1, s1);
    cudaEventRecord(ev2, s2);
    cudaStreamWaitEvent(0, ev1, 0);
    cudaStreamWaitEvent(0, ev2, 0);

    write_state_kernel<<<(B_ * H_) / 256, 256>>>(hs, sout);

    for (int c = 0; c < NCHUNK; c++) cudaEventDestroy(evA[c]);
    cudaEventDestroy(ev0);
    cudaEventDestroy(ev1);
    cudaEventDestroy(ev2);
    cudaStreamDestroy(s1);
    cudaStreamDestroy(s2);
    cudaStreamDestroy(s3);
}

// round 13
// speedup vs baseline: 1.0001x; 1.0001x over previous
#include <cuda_runtime.h>
#include <cuda_pipeline.h>
#include <cuda_fp16.h>
#include <mma.h>
#include <math.h>

using namespace nvcuda;

#define T_   64
#define B_   256
#define NIN_ 1024
#define H_   2048
#define G_   8192   // 4*H
#define NSPLIT 2    // split-K factor for recurrent GEMM
#define BHALF 128   // batch rows per stream
#define NCHUNK 8    // xw GEMM time-chunks
#define TCHUNK (T_ / NCHUNK)

// ---- scratch ----
__device__ float g_A[(size_t)T_ * B_ * G_];
__device__ float g_HWp[(size_t)NSPLIT * B_ * G_];
__device__ float g_c[(size_t)B_ * H_];
__device__ __half g_hh[(size_t)B_ * H_];
__device__ __half g_hl[(size_t)B_ * H_];
__device__ __half g_xh[(size_t)T_ * B_ * NIN_];
__device__ __half g_xl[(size_t)T_ * B_ * NIN_];
__device__ __half g_wxh[(size_t)NIN_ * G_];
__device__ __half g_wxl[(size_t)NIN_ * G_];
__device__ __half g_whh[(size_t)H_ * G_];
__device__ __half g_whl[(size_t)H_ * G_];

// ============================================================
// fp16x3 tensor-core GEMM, pre-split operands.
// C[M,N](fp32) = A[M,K] @ B[K,N];  acc = ah*bh + ah*bl + al*bh.
// Block 128x128, 8 warps (4x2), warp tile 32x64.
// BK=32, 3-stage cp.async, one __syncthreads per k-iter.
// blockIdx.z = split-K index (output C + z*zstride).
// ============================================================
#define GBM 128
#define GBN 128
#define GBK 32
#define ALD 40
#define BLD 136
#define NSTAGE 3
#define AS_H (GBM * ALD)
#define BS_H (GBK * BLD)
#define STAGE_H (2 * AS_H + 2 * BS_H)
#define SMEM_BYTES (STAGE_H * NSTAGE * 2)

__global__ __launch_bounds__(256, 2) void fp16x3_gemm(
    const __half* __restrict__ Ahi, const __half* __restrict__ Alo,
    const __half* __restrict__ Bhi, const __half* __restrict__ Blo,
    float* __restrict__ C, long long zstride, int N, int K, int K_chunk)
{
    extern __shared__ __half smem[];

    const int tid = threadIdx.x;
    const int z = blockIdx.z;
    const int kstart = z * K_chunk;

    const size_t aoff = (size_t)blockIdx.y * GBM * K + kstart;
    const size_t boff = (size_t)kstart * N + (size_t)blockIdx.x * GBN;
    const __half* Abh = Ahi + aoff;
    const __half* Abl = Alo + aoff;
    const __half* Bbh = Bhi + boff;
    const __half* Bbl = Blo + boff;

    const int warp = tid >> 5;
    const int wm = warp & 3;
    const int wn = warp >> 2;

    const int NIT = K_chunk / GBK;

    wmma::fragment<wmma::accumulator, 16, 16, 16, float> acc[2][4];
    #pragma unroll
    for (int i = 0; i < 2; i++)
        #pragma unroll
        for (int j = 0; j < 4; j++)
            wmma::fill_fragment(acc[i][j], 0.0f);

    auto prefetch = [&](int it) {
        __half* s = smem + (size_t)(it % NSTAGE) * STAGE_H;
        __half* sAh = s;
        __half* sAl = s + AS_H;
        __half* sBh = s + 2 * AS_H;
        __half* sBl = s + 2 * AS_H + BS_H;
        const int k0 = it * GBK;
        #pragma unroll
        for (int q = 0; q < 2; q++) {
            int sa = tid * 2 + q;
            int r = sa >> 2, c = (sa & 3) * 8;
            __pipeline_memcpy_async(&sAh[r * ALD + c], Abh + (size_t)r * K + k0 + c, 16);
            __pipeline_memcpy_async(&sAl[r * ALD + c], Abl + (size_t)r * K + k0 + c, 16);
            int rb = sa >> 4, cb = (sa & 15) * 8;
            __pipeline_memcpy_async(&sBh[rb * BLD + cb], Bbh + (size_t)(k0 + rb) * N + cb, 16);
            __pipeline_memcpy_async(&sBl[rb * BLD + cb], Bbl + (size_t)(k0 + rb) * N + cb, 16);
        }
    };

    prefetch(0); __pipeline_commit();
    if (NIT > 1) { prefetch(1); __pipeline_commit(); }

    for (int it = 0; it < NIT; ++it) {
        __pipeline_wait_prior((it + 1 < NIT) ? 1 : 0);
        __syncthreads();

        if (it + 2 < NIT) { prefetch(it + 2); __pipeline_commit(); }

        const __half* s = smem + (size_t)(it % NSTAGE) * STAGE_H;
        const __half* sAh = s;
        const __half* sAl = s + AS_H;
        const __half* sBh = s + 2 * AS_H;
        const __half* sBl = s + 2 * AS_H + BS_H;

        #pragma unroll
        for (int ks = 0; ks < GBK; ks += 16) {
            wmma::fragment<wmma::matrix_a, 16, 16, 16, __half, wmma::row_major> ah[2], al[2];
            #pragma unroll
            for (int i = 0; i < 2; i++) {
                wmma::load_matrix_sync(ah[i], &sAh[(wm * 32 + i * 16) * ALD + ks], ALD);
                wmma::load_matrix_sync(al[i], &sAl[(wm * 32 + i * 16) * ALD + ks], ALD);
            }
            #pragma unroll
            for (int j = 0; j < 4; j++) {
                const int colb = wn * 64 + j * 16;
                wmma::fragment<wmma::matrix_b, 16, 16, 16, __half, wmma::row_major> bf;
                wmma::load_matrix_sync(bf, &sBh[ks * BLD + colb], BLD);
                wmma::mma_sync(acc[0][j], al[0], bf, acc[0][j]);
                wmma::mma_sync(acc[1][j], al[1], bf, acc[1][j]);
                wmma::mma_sync(acc[0][j], ah[0], bf, acc[0][j]);
                wmma::mma_sync(acc[1][j], ah[1], bf, acc[1][j]);
                wmma::load_matrix_sync(bf, &sBl[ks * BLD + colb], BLD);
                wmma::mma_sync(acc[0][j], ah[0], bf, acc[0][j]);
                wmma::mma_sync(acc[1][j], ah[1], bf, acc[1][j]);
            }
        }
    }

    float* Cb = C + (size_t)z * zstride
                  + (size_t)(blockIdx.y * GBM + wm * 32) * N
                  + (size_t)blockIdx.x * GBN + wn * 64;
    #pragma unroll
    for (int i = 0; i < 2; i++)
        #pragma unroll
        for (int j = 0; j < 4; j++)
            wmma::store_matrix_sync(Cb + (size_t)(i * 16) * N + j * 16,
                                    acc[i][j], N, wmma::mem_row_major);
}

// ============================================================
__device__ __forceinline__ float fsigmoid(float x)
{
    return __fdividef(1.f, 1.f + __expf(-x));
}
__device__ __forceinline__ float ftanh(float x)
{
    return __fdividef(2.f, 1.f + __expf(-2.f * x)) - 1.f;
}

__global__ void split_kernel(const float* __restrict__ in,
                             __half* __restrict__ hi, __half* __restrict__ lo,
                             int n)
{
    int i = blockIdx.x * blockDim.x + threadIdx.x;
    if (i < n) {
        float v = in[i];
        __half h = __float2half_rn(v);
        hi[i] = h;
        lo[i] = __float2half_rn(v - __half2float(h));
    }
}

__device__ __forceinline__ void blk_reduce2_512(float& s, float& s2)
{
    __shared__ float rbuf[2][16];
    const int lane = threadIdx.x & 31;
    const int warp = threadIdx.x >> 5;
    #pragma unroll
    for (int o = 16; o; o >>= 1) {
        s  += __shfl_down_sync(0xffffffffu, s,  o);
        s2 += __shfl_down_sync(0xffffffffu, s2, o);
    }
    if (lane == 0) { rbuf[0][warp] = s; rbuf[1][warp] = s2; }
    __syncthreads();
    if (warp == 0) {
        s  = (lane < 16) ? rbuf[0][lane] : 0.f;
        s2 = (lane < 16) ? rbuf[1][lane] : 0.f;
        #pragma unroll
        for (int o = 8; o; o >>= 1) {
            s  += __shfl_down_sync(0xffffffffu, s,  o);
            s2 += __shfl_down_sync(0xffffffffu, s2, o);
        }
        if (lane == 0) { rbuf[0][0] = s; rbuf[1][0] = s2; }
    }
    __syncthreads();
    s  = rbuf[0][0];
    s2 = rbuf[1][0];
    __syncthreads();
}

__device__ __forceinline__ void blk_reduce2(float& s, float& s2)
{
    __shared__ float rbuf[2][8];
    const int lane = threadIdx.x & 31;
    const int warp = threadIdx.x >> 5;
    #pragma unroll
    for (int o = 16; o; o >>= 1) {
        s  += __shfl_down_sync(0xffffffffu, s,  o);
        s2 += __shfl_down_sync(0xffffffffu, s2, o);
    }
    if (lane == 0) { rbuf[0][warp] = s; rbuf[1][warp] = s2; }
    __syncthreads();
    if (warp == 0) {
        s  = (lane < 8) ? rbuf[0][lane] : 0.f;
        s2 = (lane < 8) ? rbuf[1][lane] : 0.f;
        #pragma unroll
        for (int o = 4; o; o >>= 1) {
            s  += __shfl_down_sync(0xffffffffu, s,  o);
            s2 += __shfl_down_sync(0xffffffffu, s2, o);
        }
        if (lane == 0) { rbuf[0][0] = s; rbuf[1][0] = s2; }
    }
    __syncthreads();
    s  = rbuf[0][0];
    s2 = rbuf[1][0];
    __syncthreads();
}

__global__ __launch_bounds__(256) void ln_rows_add_kernel(
    const float* __restrict__ Cin, const float* __restrict__ gamma,
    const float* __restrict__ beta, const float* __restrict__ bias,
    float* __restrict__ Aout)
{
    const int row = blockIdx.x;
    const float* x = Cin + (size_t)row * G_;
    float s = 0.f, s2 = 0.f;
    for (int j = threadIdx.x; j < G_; j += 256) {
        float v = x[j]; s += v; s2 += v * v;
    }
    blk_reduce2(s, s2);
    const float inv = 1.f / (float)G_;
    float mu   = s * inv;
    float rstd = rsqrtf(s2 * inv - mu * mu + 1e-5f);
    float* o = Aout + (size_t)row * G_;
    for (int j = threadIdx.x; j < G_; j += 256) {
        o[j] = (x[j] - mu) * rstd * gamma[j] + beta[j] + bias[j];
    }
}

__global__ void init_state_kernel(const float* __restrict__ init,
                                  const float* __restrict__ mask)
{
    int idx = blockIdx.x * blockDim.x + threadIdx.x;
    int b = idx >> 11;
    int j = idx & (H_ - 1);
    size_t base = (size_t)b * T_ * 2 * H_;
    g_c[idx] = init[base + j];
    float h = init[base + H_ + j] * (1.f - mask[b]);
    __half hh = __float2half_rn(h);
    g_hh[idx] = hh;
    g_hl[idx] = __float2half_rn(h - __half2float(hh));
}

// ============================================================
// Fused cell for one batch half (grid = BHALF blocks, 512 thr).
// ============================================================
__global__ __launch_bounds__(512) void cell_kernel(
    int t, int b0, const float* __restrict__ mask,
    const float* __restrict__ A,
    const float* __restrict__ gh, const float* __restrict__ bh,
    const float* __restrict__ gc, const float* __restrict__ bc,
    float* __restrict__ hs)
{
    const int b = blockIdx.x + b0;
    const int tid = threadIdx.x;
    const float keep = 1.f - mask[t * B_ + b];
    const float keep_next = (t + 1 < T_) ? (1.f - mask[(t + 1) * B_ + b]) : 1.f;
    const float* hw0 = g_HWp + (size_t)b * G_;
    const size_t PS = (size_t)B_ * G_;
    const float* a = A + ((size_t)t * B_ + b) * G_;

    float s = 0.f, s2 = 0.f;
    #pragma unroll
    for (int p = 0; p < G_ / (512 * 4); p++) {
        int i4 = (tid + p * 512) * 4;
        float4 p0 = *(const float4*)(hw0 + i4);
        float4 p1 = *(const float4*)(hw0 + PS + i4);
        float v0 = p0.x + p1.x, v1 = p0.y + p1.y;
        float v2 = p0.z + p1.z, v3 = p0.w + p1.w;
        s  += v0 + v1 + v2 + v3;
        s2 += v0 * v0 + v1 * v1 + v2 * v2 + v3 * v3;
    }
    blk_reduce2_512(s, s2);
    const float invG = 1.f / (float)G_;
    float mu   = s * invG;
    float rstd = rsqrtf(s2 * invG - mu * mu + 1e-5f);

    const int j0 = tid * 4;
    float cs = 0.f, cs2 = 0.f;
    float cn4[4], og4[4];
    {
        float4 hwi = *(const float4*)(hw0 + j0);
        float4 hwf = *(const float4*)(hw0 + H_ + j0);
        float4 hwo = *(const float4*)(hw0 + 2 * H_ + j0);
        float4 hwu = *(const float4*)(hw0 + 3 * H_ + j0);
        float4 q;
        q = *(const float4*)(hw0 + PS + j0);            hwi.x += q.x; hwi.y += q.y; hwi.z += q.z; hwi.w += q.w;
        q = *(const float4*)(hw0 + PS + H_ + j0);       hwf.x += q.x; hwf.y += q.y; hwf.z += q.z; hwf.w += q.w;
        q = *(const float4*)(hw0 + PS + 2 * H_ + j0);   hwo.x += q.x; hwo.y += q.y; hwo.z += q.z; hwo.w += q.w;
        q = *(const float4*)(hw0 + PS + 3 * H_ + j0);   hwu.x += q.x; hwu.y += q.y; hwu.z += q.z; hwu.w += q.w;

        float4 ai = *(const float4*)(a + j0);
        float4 af = *(const float4*)(a + H_ + j0);
        float4 ao = *(const float4*)(a + 2 * H_ + j0);
        float4 au = *(const float4*)(a + 3 * H_ + j0);
        float4 ghi = *(const float4*)(gh + j0);
        float4 ghf = *(const float4*)(gh + H_ + j0);
        float4 gho = *(const float4*)(gh + 2 * H_ + j0);
        float4 ghu = *(const float4*)(gh + 3 * H_ + j0);
        float4 bhi = *(const float4*)(bh + j0);
        float4 bhf = *(const float4*)(bh + H_ + j0);
        float4 bho = *(const float4*)(bh + 2 * H_ + j0);
        float4 bhu = *(const float4*)(bh + 3 * H_ + j0);
        float4 cc  = *(const float4*)(&g_c[(size_t)b * H_ + j0]);

        float hwi_[4] = {hwi.x, hwi.y, hwi.z, hwi.w};
        float hwf_[4] = {hwf.x, hwf.y, hwf.z, hwf.w};
        float hwo_[4] = {hwo.x, hwo.y, hwo.z, hwo.w};
        float hwu_[4] = {hwu.x, hwu.y, hwu.z, hwu.w};
        float ai_[4]  = {ai.x, ai.y, ai.z, ai.w};
        float af_[4]  = {af.x, af.y, af.z, af.w};
        float ao_[4]  = {ao.x, ao.y, ao.z, ao.w};
        float au_[4]  = {au.x, au.y, au.z, au.w};
        float ghi_[4] = {ghi.x, ghi.y, ghi.z, ghi.w};
        float ghf_[4] = {ghf.x, ghf.y, ghf.z, ghf.w};
        float gho_[4] = {gho.x, gho.y, gho.z, gho.w};
        float ghu_[4] = {ghu.x, ghu.y, ghu.z, ghu.w};
        float bhi_[4] = {bhi.x, bhi.y, bhi.z, bhi.w};
        float bhf_[4] = {bhf.x, bhf.y, bhf.z, bhf.w};
        float bho_[4] = {bho.x, bho.y, bho.z, bho.w};
        float bhu_[4] = {bhu.x, bhu.y, bhu.z, bhu.w};
        float cc_[4]  = {cc.x, cc.y, cc.z, cc.w};

        #pragma unroll
        for (int q4 = 0; q4 < 4; q4++) {
            float zi = ai_[q4] + (hwi_[q4] - mu) * rstd * ghi_[q4] + bhi_[q4];
            float zf = af_[q4] + (hwf_[q4] - mu) * rstd * ghf_[q4] + bhf_[q4];
            float zo = ao_[q4] + (hwo_[q4] - mu) * rstd * gho_[q4] + bho_[q4];
            float zu = au_[q4] + (hwu_[q4] - mu) * rstd * ghu_[q4] + bhu_[q4];
            float ig = fsigmoid(zi);
            float fg = fsigmoid(zf);
            float og = fsigmoid(zo);
            float ug = ftanh(zu);
            float cn = fg * (cc_[q4] * keep) + ig * ug;
            cn4[q4] = cn;
            og4[q4] = og;
            cs += cn; cs2 += cn * cn;
        }
        *(float4*)(&g_c[(size_t)b * H_ + j0]) =
            make_float4(cn4[0], cn4[1], cn4[2], cn4[3]);
    }
    blk_reduce2_512(cs, cs2);
    const float invH = 1.f / (float)H_;
    float muc   = cs * invH;
    float rstdc = rsqrtf(cs2 * invH - muc * muc + 1e-5f);

    {
        float4 gc4 = *(const float4*)(gc + j0);
        float4 bc4 = *(const float4*)(bc + j0);
        float gc_[4] = {gc4.x, gc4.y, gc4.z, gc4.w};
        float bc_[4] = {bc4.x, bc4.y, bc4.z, bc4.w};
        float hn[4];
        __half hhp[4], hlp[4];
        #pragma unroll
        for (int q4 = 0; q4 < 4; q4++) {
            float v = og4[q4] * ftanh((cn4[q4] - muc) * rstdc * gc_[q4] + bc_[q4]);
            hn[q4] = v;
            float hm = v * keep_next;
            __half hhi = __float2half_rn(hm);
            hhp[q4] = hhi;
            hlp[q4] = __float2half_rn(hm - __half2float(hhi));
        }
        *(float4*)(hs + ((size_t)t * B_ + b) * H_ + j0) =
            make_float4(hn[0], hn[1], hn[2], hn[3]);
        __half2* ph = (__half2*)(&g_hh[(size_t)b * H_ + j0]);
        ph[0] = __halves2half2(hhp[0], hhp[1]);
        ph[1] = __halves2half2(hhp[2], hhp[3]);
        __half2* pl = (__half2*)(&g_hl[(size_t)b * H_ + j0]);
        pl[0] = __halves2half2(hlp[0], hlp[1]);
        pl[1] = __halves2half2(hlp[2], hlp[3]);
    }
}

__global__ void write_state_kernel(const float* __restrict__ hs,
                                   float* __restrict__ sout)
{
    int idx = blockIdx.x * blockDim.x + threadIdx.x;
    int b = idx >> 11;
    int j = idx & (H_ - 1);
    sout[(size_t)b * 2 * H_ + j] = g_c[idx];
    sout[(size_t)b * 2 * H_ + H_ + j] =
        hs[((size_t)(T_ - 1) * B_ + b) * H_ + j];
}

// ============================================================
extern "C" void kernel_launch(void* const* d_in, const int* in_sizes, int n_in,
                              void* d_out, int out_size)
{
    const float* x    = (const float*)d_in[0];
    const float* mask = (const float*)d_in[1];
    const float* init = (const float*)d_in[2];
    const float* wx   = (const float*)d_in[3];
    const float* wh   = (const float*)d_in[4];
    const float* bvec = (const float*)d_in[5];
    const float* gx   = (const float*)d_in[6];
    const float* bx   = (const float*)d_in[7];
    const float* gh   = (const float*)d_in[8];
    const float* bh   = (const float*)d_in[9];
    const float* gc   = (const float*)d_in[10];
    const float* bc   = (const float*)d_in[11];

    float* out  = (float*)d_out;
    float* hs   = out;
    float* sout = out + (size_t)T_ * B_ * H_;

    float *Abuf, *HWp;
    __half *xh, *xl, *wxh, *wxl, *whh, *whl, *hh, *hl;
    cudaGetSymbolAddress((void**)&Abuf, g_A);
    cudaGetSymbolAddress((void**)&HWp,  g_HWp);
    cudaGetSymbolAddress((void**)&xh,   g_xh);
    cudaGetSymbolAddress((void**)&xl,   g_xl);
    cudaGetSymbolAddress((void**)&wxh,  g_wxh);
    cudaGetSymbolAddress((void**)&wxl,  g_wxl);
    cudaGetSymbolAddress((void**)&whh,  g_whh);
    cudaGetSymbolAddress((void**)&whl,  g_whl);
    cudaGetSymbolAddress((void**)&hh,   g_hh);
    cudaGetSymbolAddress((void**)&hl,   g_hl);

    cudaFuncSetAttribute(fp16x3_gemm,
                         cudaFuncAttributeMaxDynamicSharedMemorySize, SMEM_BYTES);

    const int MCH = TCHUNK * B_;   // rows per xw chunk = 2048

    // ---- serial prologue on the capture stream ----
    {
        int nx = T_ * B_ * NIN_;
        split_kernel<<<(nx + 255) / 256, 256>>>(x, xh, xl, nx);
        int nwx = NIN_ * G_;
        split_kernel<<<(nwx + 255) / 256, 256>>>(wx, wxh, wxl, nwx);
        int nwh = H_ * G_;
        split_kernel<<<(nwh + 255) / 256, 256>>>(wh, whh, whl, nwh);
    }
    init_state_kernel<<<(B_ * H_) / 256, 256>>>(init, mask);
    // chunk 0 of A (needed by cell(0..7)) stays on the critical path
    fp16x3_gemm<<<dim3(G_ / GBN, MCH / GBM, 1), 256, SMEM_BYTES>>>(
        xh, xl, wxh, wxl, Abuf, 0, G_, NIN_, NIN_);
    ln_rows_add_kernel<<<MCH, 256>>>(Abuf, gx, bx, bvec, Abuf);

    // ---- fork: high-priority recurrence streams, low-priority producer ----
    int prLo, prHi;
    cudaDeviceGetStreamPriorityRange(&prLo, &prHi);
    cudaStream_t s1, s2, s3;
    cudaStreamCreateWithPriority(&s1, cudaStreamNonBlocking, prHi);
    cudaStreamCreateWithPriority(&s2, cudaStreamNonBlocking, prHi);
    cudaStreamCreateWithPriority(&s3, cudaStreamNonBlocking, prLo);
    cudaEvent_t ev0, ev1, ev2;
    cudaEventCreateWithFlags(&ev0, cudaEventDisableTiming);
    cudaEventCreateWithFlags(&ev1, cudaEventDisableTiming);
    cudaEventCreateWithFlags(&ev2, cudaEventDisableTiming);
    cudaEvent_t evA[NCHUNK];
    for (int c = 1; c < NCHUNK; c++)
        cudaEventCreateWithFlags(&evA[c], cudaEventDisableTiming);

    cudaEventRecord(ev0, 0);
    cudaStreamWaitEvent(s1, ev0, 0);
    cudaStreamWaitEvent(s2, ev0, 0);
    cudaStreamWaitEvent(s3, ev0, 0);

    // xw chunks 1..7 at LOW priority (backfill idle SMs only)
    for (int c = 1; c < NCHUNK; c++) {
        const __half* xch = xh + (size_t)c * MCH * NIN_;
        const __half* xcl = xl + (size_t)c * MCH * NIN_;
        float* Ach = Abuf + (size_t)c * MCH * G_;
        fp16x3_gemm<<<dim3(G_ / GBN, MCH / GBM, 1), 256, SMEM_BYTES, s3>>>(
            xch, xcl, wxh, wxl, Ach, 0, G_, NIN_, NIN_);
        ln_rows_add_kernel<<<MCH, 256, 0, s3>>>(Ach, gx, bx, bvec, Ach);
        cudaEventRecord(evA[c], s3);
    }

    const int KCH = H_ / NSPLIT;
    const long long ZST = (long long)B_ * G_;

    for (int t = 0; t < T_; t++) {
        if (t % TCHUNK == 0 && t > 0) {
            cudaStreamWaitEvent(s1, evA[t / TCHUNK], 0);
            cudaStreamWaitEvent(s2, evA[t / TCHUNK], 0);
        }
        fp16x3_gemm<<<dim3(G_ / GBN, BHALF / GBM, NSPLIT), 256, SMEM_BYTES, s1>>>(
            hh, hl, whh, whl, HWp, ZST, G_, H_, KCH);
        cell_kernel<<<BHALF, 512, 0, s1>>>(t, 0, mask, Abuf, gh, bh, gc, bc, hs);
        fp16x3_gemm<<<dim3(G_ / GBN, BHALF / GBM, NSPLIT), 256, SMEM_BYTES, s2>>>(
            hh + (size_t)BHALF * H_, hl + (size_t)BHALF * H_, whh, whl,
            HWp + (size_t)BHALF * G_, ZST, G_, H_, KCH);
        cell_kernel<<<BHALF, 512, 0, s2>>>(t, BHALF, mask, Abuf, gh, bh, gc, bc, hs);
    }

    cudaEventRecord(ev1, s1);
    cudaEventRecord(ev2, s2);
    cudaStreamWaitEvent(0, ev1, 0);
    cudaStreamWaitEvent(0, ev2, 0);

    write_state_kernel<<<(B_ * H_) / 256, 256>>>(hs, sout);

    for (int c = 1; c < NCHUNK; c++) cudaEventDestroy(evA[c]);
    cudaEventDestroy(ev0);
    cudaEventDestroy(ev1);
    cudaEventDestroy(ev2);
    cudaStreamDestroy(s1);
    cudaStreamDestroy(s2);
    cudaStreamDestroy(s3);
}

// round 14
// speedup vs baseline: 1.0533x; 1.0532x over previous
#include <cuda_runtime.h>
#include <cuda_pipeline.h>
#include <cuda_fp16.h>
#include <mma.h>
#include <math.h>

using namespace nvcuda;

#define T_   64
#define B_   256
#define NIN_ 1024
#define H_   2048
#define G_   8192   // 4*H
#define NSPLIT 2    // split-K factor for recurrent GEMM
#define BHALF 128   // batch rows per stream

// ---- scratch ----
__device__ float g_A[(size_t)T_ * B_ * G_];
__device__ float g_HWp[(size_t)NSPLIT * B_ * G_];
__device__ float g_c[(size_t)B_ * H_];
__device__ __half g_hh[(size_t)B_ * H_];
__device__ __half g_hl[(size_t)B_ * H_];
__device__ __half g_xh[(size_t)T_ * B_ * NIN_];
__device__ __half g_xl[(size_t)T_ * B_ * NIN_];
__device__ __half g_wxh[(size_t)NIN_ * G_];
__device__ __half g_wxl[(size_t)NIN_ * G_];
__device__ __half g_whh[(size_t)H_ * G_];
__device__ __half g_whl[(size_t)H_ * G_];

// ============================================================
// fp16x3 tensor-core GEMM, pre-split operands.
// C[M,N](fp32) = A[M,K] @ B[K,N];  acc = ah*bh + ah*bl + al*bh.
// Block 128x128, 8 warps (4x2), warp tile 32x64.
// BK=32, 3-stage cp.async, one __syncthreads per k-iter.
// blockIdx.z = split-K index (output C + z*zstride).
// ============================================================
#define GBM 128
#define GBN 128
#define GBK 32
#define ALD 40
#define BLD 136
#define NSTAGE 3
#define AS_H (GBM * ALD)
#define BS_H (GBK * BLD)
#define STAGE_H (2 * AS_H + 2 * BS_H)
#define SMEM_BYTES (STAGE_H * NSTAGE * 2)

__global__ __launch_bounds__(256, 2) void fp16x3_gemm(
    const __half* __restrict__ Ahi, const __half* __restrict__ Alo,
    const __half* __restrict__ Bhi, const __half* __restrict__ Blo,
    float* __restrict__ C, long long zstride, int N, int K, int K_chunk)
{
    extern __shared__ __half smem[];

    const int tid = threadIdx.x;
    const int z = blockIdx.z;
    const int kstart = z * K_chunk;

    const size_t aoff = (size_t)blockIdx.y * GBM * K + kstart;
    const size_t boff = (size_t)kstart * N + (size_t)blockIdx.x * GBN;
    const __half* Abh = Ahi + aoff;
    const __half* Abl = Alo + aoff;
    const __half* Bbh = Bhi + boff;
    const __half* Bbl = Blo + boff;

    const int warp = tid >> 5;
    const int wm = warp & 3;
    const int wn = warp >> 2;

    const int NIT = K_chunk / GBK;

    wmma::fragment<wmma::accumulator, 16, 16, 16, float> acc[2][4];
    #pragma unroll
    for (int i = 0; i < 2; i++)
        #pragma unroll
        for (int j = 0; j < 4; j++)
            wmma::fill_fragment(acc[i][j], 0.0f);

    auto prefetch = [&](int it) {
        __half* s = smem + (size_t)(it % NSTAGE) * STAGE_H;
        __half* sAh = s;
        __half* sAl = s + AS_H;
        __half* sBh = s + 2 * AS_H;
        __half* sBl = s + 2 * AS_H + BS_H;
        const int k0 = it * GBK;
        #pragma unroll
        for (int q = 0; q < 2; q++) {
            int sa = tid * 2 + q;
            int r = sa >> 2, c = (sa & 3) * 8;
            __pipeline_memcpy_async(&sAh[r * ALD + c], Abh + (size_t)r * K + k0 + c, 16);
            __pipeline_memcpy_async(&sAl[r * ALD + c], Abl + (size_t)r * K + k0 + c, 16);
            int rb = sa >> 4, cb = (sa & 15) * 8;
            __pipeline_memcpy_async(&sBh[rb * BLD + cb], Bbh + (size_t)(k0 + rb) * N + cb, 16);
            __pipeline_memcpy_async(&sBl[rb * BLD + cb], Bbl + (size_t)(k0 + rb) * N + cb, 16);
        }
    };

    prefetch(0); __pipeline_commit();
    if (NIT > 1) { prefetch(1); __pipeline_commit(); }

    for (int it = 0; it < NIT; ++it) {
        __pipeline_wait_prior((it + 1 < NIT) ? 1 : 0);
        __syncthreads();

        if (it + 2 < NIT) { prefetch(it + 2); __pipeline_commit(); }

        const __half* s = smem + (size_t)(it % NSTAGE) * STAGE_H;
        const __half* sAh = s;
        const __half* sAl = s + AS_H;
        const __half* sBh = s + 2 * AS_H;
        const __half* sBl = s + 2 * AS_H + BS_H;

        #pragma unroll
        for (int ks = 0; ks < GBK; ks += 16) {
            wmma::fragment<wmma::matrix_a, 16, 16, 16, __half, wmma::row_major> ah[2], al[2];
            #pragma unroll
            for (int i = 0; i < 2; i++) {
                wmma::load_matrix_sync(ah[i], &sAh[(wm * 32 + i * 16) * ALD + ks], ALD);
                wmma::load_matrix_sync(al[i], &sAl[(wm * 32 + i * 16) * ALD + ks], ALD);
            }
            #pragma unroll
            for (int j = 0; j < 4; j++) {
                const int colb = wn * 64 + j * 16;
                wmma::fragment<wmma::matrix_b, 16, 16, 16, __half, wmma::row_major> bf;
                wmma::load_matrix_sync(bf, &sBh[ks * BLD + colb], BLD);
                wmma::mma_sync(acc[0][j], al[0], bf, acc[0][j]);
                wmma::mma_sync(acc[1][j], al[1], bf, acc[1][j]);
                wmma::mma_sync(acc[0][j], ah[0], bf, acc[0][j]);
                wmma::mma_sync(acc[1][j], ah[1], bf, acc[1][j]);
                wmma::load_matrix_sync(bf, &sBl[ks * BLD + colb], BLD);
                wmma::mma_sync(acc[0][j], ah[0], bf, acc[0][j]);
                wmma::mma_sync(acc[1][j], ah[1], bf, acc[1][j]);
            }
        }
    }

    float* Cb = C + (size_t)z * zstride
                  + (size_t)(blockIdx.y * GBM + wm * 32) * N
                  + (size_t)blockIdx.x * GBN + wn * 64;
    #pragma unroll
    for (int i = 0; i < 2; i++)
        #pragma unroll
        for (int j = 0; j < 4; j++)
            wmma::store_matrix_sync(Cb + (size_t)(i * 16) * N + j * 16,
                                    acc[i][j], N, wmma::mem_row_major);
}

// ============================================================
__device__ __forceinline__ float fsigmoid(float x)
{
    return __fdividef(1.f, 1.f + __expf(-x));
}
__device__ __forceinline__ float ftanh(float x)
{
    return __fdividef(2.f, 1.f + __expf(-2.f * x)) - 1.f;
}

__global__ void split_kernel(const float* __restrict__ in,
                             __half* __restrict__ hi, __half* __restrict__ lo,
                             int n)
{
    int i = blockIdx.x * blockDim.x + threadIdx.x;
    if (i < n) {
        float v = in[i];
        __half h = __float2half_rn(v);
        hi[i] = h;
        lo[i] = __float2half_rn(v - __half2float(h));
    }
}

__device__ __forceinline__ void blk_reduce2_512(float& s, float& s2)
{
    __shared__ float rbuf[2][16];
    const int lane = threadIdx.x & 31;
    const int warp = threadIdx.x >> 5;
    #pragma unroll
    for (int o = 16; o; o >>= 1) {
        s  += __shfl_down_sync(0xffffffffu, s,  o);
        s2 += __shfl_down_sync(0xffffffffu, s2, o);
    }
    if (lane == 0) { rbuf[0][warp] = s; rbuf[1][warp] = s2; }
    __syncthreads();
    if (warp == 0) {
        s  = (lane < 16) ? rbuf[0][lane] : 0.f;
        s2 = (lane < 16) ? rbuf[1][lane] : 0.f;
        #pragma unroll
        for (int o = 8; o; o >>= 1) {
            s  += __shfl_down_sync(0xffffffffu, s,  o);
            s2 += __shfl_down_sync(0xffffffffu, s2, o);
        }
        if (lane == 0) { rbuf[0][0] = s; rbuf[1][0] = s2; }
    }
    __syncthreads();
    s  = rbuf[0][0];
    s2 = rbuf[1][0];
    __syncthreads();
}

__device__ __forceinline__ void blk_reduce2(float& s, float& s2)
{
    __shared__ float rbuf[2][8];
    const int lane = threadIdx.x & 31;
    const int warp = threadIdx.x >> 5;
    #pragma unroll
    for (int o = 16; o; o >>= 1) {
        s  += __shfl_down_sync(0xffffffffu, s,  o);
        s2 += __shfl_down_sync(0xffffffffu, s2, o);
    }
    if (lane == 0) { rbuf[0][warp] = s; rbuf[1][warp] = s2; }
    __syncthreads();
    if (warp == 0) {
        s  = (lane < 8) ? rbuf[0][lane] : 0.f;
        s2 = (lane < 8) ? rbuf[1][lane] : 0.f;
        #pragma unroll
        for (int o = 4; o; o >>= 1) {
            s  += __shfl_down_sync(0xffffffffu, s,  o);
            s2 += __shfl_down_sync(0xffffffffu, s2, o);
        }
        if (lane == 0) { rbuf[0][0] = s; rbuf[1][0] = s2; }
    }
    __syncthreads();
    s  = rbuf[0][0];
    s2 = rbuf[1][0];
    __syncthreads();
}

__global__ __launch_bounds__(256) void ln_rows_add_kernel(
    const float* __restrict__ Cin, const float* __restrict__ gamma,
    const float* __restrict__ beta, const float* __restrict__ bias,
    float* __restrict__ Aout)
{
    const int row = blockIdx.x;
    const float* x = Cin + (size_t)row * G_;
    float s = 0.f, s2 = 0.f;
    for (int j = threadIdx.x; j < G_; j += 256) {
        float v = x[j]; s += v; s2 += v * v;
    }
    blk_reduce2(s, s2);
    const float inv = 1.f / (float)G_;
    float mu   = s * inv;
    float rstd = rsqrtf(s2 * inv - mu * mu + 1e-5f);
    float* o = Aout + (size_t)row * G_;
    for (int j = threadIdx.x; j < G_; j += 256) {
        o[j] = (x[j] - mu) * rstd * gamma[j] + beta[j] + bias[j];
    }
}

__global__ void init_state_kernel(const float* __restrict__ init,
                                  const float* __restrict__ mask)
{
    int idx = blockIdx.x * blockDim.x + threadIdx.x;
    int b = idx >> 11;
    int j = idx & (H_ - 1);
    size_t base = (size_t)b * T_ * 2 * H_;
    g_c[idx] = init[base + j];
    float h = init[base + H_ + j] * (1.f - mask[b]);
    __half hh = __float2half_rn(h);
    g_hh[idx] = hh;
    g_hl[idx] = __float2half_rn(h - __half2float(hh));
}

// ============================================================
// Fused cell for one batch half (grid = BHALF blocks, 512 thr).
// No block smem beyond the reduce buffers; og stays in registers.
// ============================================================
__global__ __launch_bounds__(512) void cell_kernel(
    int t, int b0, const float* __restrict__ mask,
    const float* __restrict__ A,
    const float* __restrict__ gh, const float* __restrict__ bh,
    const float* __restrict__ gc, const float* __restrict__ bc,
    float* __restrict__ hs)
{
    const int b = blockIdx.x + b0;
    const int tid = threadIdx.x;
    const float keep = 1.f - mask[t * B_ + b];
    const float keep_next = (t + 1 < T_) ? (1.f - mask[(t + 1) * B_ + b]) : 1.f;
    const float* hw0 = g_HWp + (size_t)b * G_;
    const size_t PS = (size_t)B_ * G_;
    const float* a = A + ((size_t)t * B_ + b) * G_;

    float s = 0.f, s2 = 0.f;
    #pragma unroll
    for (int p = 0; p < G_ / (512 * 4); p++) {
        int i4 = (tid + p * 512) * 4;
        float4 p0 = *(const float4*)(hw0 + i4);
        float4 p1 = *(const float4*)(hw0 + PS + i4);
        float v0 = p0.x + p1.x, v1 = p0.y + p1.y;
        float v2 = p0.z + p1.z, v3 = p0.w + p1.w;
        s  += v0 + v1 + v2 + v3;
        s2 += v0 * v0 + v1 * v1 + v2 * v2 + v3 * v3;
    }
    blk_reduce2_512(s, s2);
    const float invG = 1.f / (float)G_;
    float mu   = s * invG;
    float rstd = rsqrtf(s2 * invG - mu * mu + 1e-5f);

    const int j0 = tid * 4;
    float cs = 0.f, cs2 = 0.f;
    float cn4[4], og4[4];
    {
        float4 hwi = *(const float4*)(hw0 + j0);
        float4 hwf = *(const float4*)(hw0 + H_ + j0);
        float4 hwo = *(const float4*)(hw0 + 2 * H_ + j0);
        float4 hwu = *(const float4*)(hw0 + 3 * H_ + j0);
        float4 q;
        q = *(const float4*)(hw0 + PS + j0);            hwi.x += q.x; hwi.y += q.y; hwi.z += q.z; hwi.w += q.w;
        q = *(const float4*)(hw0 + PS + H_ + j0);       hwf.x += q.x; hwf.y += q.y; hwf.z += q.z; hwf.w += q.w;
        q = *(const float4*)(hw0 + PS + 2 * H_ + j0);   hwo.x += q.x; hwo.y += q.y; hwo.z += q.z; hwo.w += q.w;
        q = *(const float4*)(hw0 + PS + 3 * H_ + j0);   hwu.x += q.x; hwu.y += q.y; hwu.z += q.z; hwu.w += q.w;

        float4 ai = *(const float4*)(a + j0);
        float4 af = *(const float4*)(a + H_ + j0);
        float4 ao = *(const float4*)(a + 2 * H_ + j0);
        float4 au = *(const float4*)(a + 3 * H_ + j0);
        float4 ghi = *(const float4*)(gh + j0);
        float4 ghf = *(const float4*)(gh + H_ + j0);
        float4 gho = *(const float4*)(gh + 2 * H_ + j0);
        float4 ghu = *(const float4*)(gh + 3 * H_ + j0);
        float4 bhi = *(const float4*)(bh + j0);
        float4 bhf = *(const float4*)(bh + H_ + j0);
        float4 bho = *(const float4*)(bh + 2 * H_ + j0);
        float4 bhu = *(const float4*)(bh + 3 * H_ + j0);
        float4 cc  = *(const float4*)(&g_c[(size_t)b * H_ + j0]);

        float hwi_[4] = {hwi.x, hwi.y, hwi.z, hwi.w};
        float hwf_[4] = {hwf.x, hwf.y, hwf.z, hwf.w};
        float hwo_[4] = {hwo.x, hwo.y, hwo.z, hwo.w};
        float hwu_[4] = {hwu.x, hwu.y, hwu.z, hwu.w};
        float ai_[4]  = {ai.x, ai.y, ai.z, ai.w};
        float af_[4]  = {af.x, af.y, af.z, af.w};
        float ao_[4]  = {ao.x, ao.y, ao.z, ao.w};
        float au_[4]  = {au.x, au.y, au.z, au.w};
        float ghi_[4] = {ghi.x, ghi.y, ghi.z, ghi.w};
        float ghf_[4] = {ghf.x, ghf.y, ghf.z, ghf.w};
        float gho_[4] = {gho.x, gho.y, gho.z, gho.w};
        float ghu_[4] = {ghu.x, ghu.y, ghu.z, ghu.w};
        float bhi_[4] = {bhi.x, bhi.y, bhi.z, bhi.w};
        float bhf_[4] = {bhf.x, bhf.y, bhf.z, bhf.w};
        float bho_[4] = {bho.x, bho.y, bho.z, bho.w};
        float bhu_[4] = {bhu.x, bhu.y, bhu.z, bhu.w};
        float cc_[4]  = {cc.x, cc.y, cc.z, cc.w};

        #pragma unroll
        for (int q4 = 0; q4 < 4; q4++) {
            float zi = ai_[q4] + (hwi_[q4] - mu) * rstd * ghi_[q4] + bhi_[q4];
            float zf = af_[q4] + (hwf_[q4] - mu) * rstd * ghf_[q4] + bhf_[q4];
            float zo = ao_[q4] + (hwo_[q4] - mu) * rstd * gho_[q4] + bho_[q4];
            float zu = au_[q4] + (hwu_[q4] - mu) * rstd * ghu_[q4] + bhu_[q4];
            float ig = fsigmoid(zi);
            float fg = fsigmoid(zf);
            float og = fsigmoid(zo);
            float ug = ftanh(zu);
            float cn = fg * (cc_[q4] * keep) + ig * ug;
            cn4[q4] = cn;
            og4[q4] = og;
            cs += cn; cs2 += cn * cn;
        }
        *(float4*)(&g_c[(size_t)b * H_ + j0]) =
            make_float4(cn4[0], cn4[1], cn4[2], cn4[3]);
    }
    blk_reduce2_512(cs, cs2);
    const float invH = 1.f / (float)H_;
    float muc   = cs * invH;
    float rstdc = rsqrtf(cs2 * invH - muc * muc + 1e-5f);

    {
        float4 gc4 = *(const float4*)(gc + j0);
        float4 bc4 = *(const float4*)(bc + j0);
        float gc_[4] = {gc4.x, gc4.y, gc4.z, gc4.w};
        float bc_[4] = {bc4.x, bc4.y, bc4.z, bc4.w};
        float hn[4];
        __half hhp[4], hlp[4];
        #pragma unroll
        for (int q4 = 0; q4 < 4; q4++) {
            float v = og4[q4] * ftanh((cn4[q4] - muc) * rstdc * gc_[q4] + bc_[q4]);
            hn[q4] = v;
            float hm = v * keep_next;
            __half hhi = __float2half_rn(hm);
            hhp[q4] = hhi;
            hlp[q4] = __float2half_rn(hm - __half2float(hhi));
        }
        *(float4*)(hs + ((size_t)t * B_ + b) * H_ + j0) =
            make_float4(hn[0], hn[1], hn[2], hn[3]);
        __half2* ph = (__half2*)(&g_hh[(size_t)b * H_ + j0]);
        ph[0] = __halves2half2(hhp[0], hhp[1]);
        ph[1] = __halves2half2(hhp[2], hhp[3]);
        __half2* pl = (__half2*)(&g_hl[(size_t)b * H_ + j0]);
        pl[0] = __halves2half2(hlp[0], hlp[1]);
        pl[1] = __halves2half2(hlp[2], hlp[3]);
    }
}

__global__ void write_state_kernel(const float* __restrict__ hs,
                                   float* __restrict__ sout)
{
    int idx = blockIdx.x * blockDim.x + threadIdx.x;
    int b = idx >> 11;
    int j = idx & (H_ - 1);
    sout[(size_t)b * 2 * H_ + j] = g_c[idx];
    sout[(size_t)b * 2 * H_ + H_ + j] =
        hs[((size_t)(T_ - 1) * B_ + b) * H_ + j];
}

// ============================================================
extern "C" void kernel_launch(void* const* d_in, const int* in_sizes, int n_in,
                              void* d_out, int out_size)
{
    const float* x    = (const float*)d_in[0];
    const float* mask = (const float*)d_in[1];
    const float* init = (const float*)d_in[2];
    const float* wx   = (const float*)d_in[3];
    const float* wh   = (const float*)d_in[4];
    const float* bvec = (const float*)d_in[5];
    const float* gx   = (const float*)d_in[6];
    const float* bx   = (const float*)d_in[7];
    const float* gh   = (const float*)d_in[8];
    const float* bh   = (const float*)d_in[9];
    const float* gc   = (const float*)d_in[10];
    const float* bc   = (const float*)d_in[11];

    float* out  = (float*)d_out;
    float* hs   = out;
    float* sout = out + (size_t)T_ * B_ * H_;

    float *Abuf, *HWp;
    __half *xh, *xl, *wxh, *wxl, *whh, *whl, *hh, *hl;
    cudaGetSymbolAddress((void**)&Abuf, g_A);
    cudaGetSymbolAddress((void**)&HWp,  g_HWp);
    cudaGetSymbolAddress((void**)&xh,   g_xh);
    cudaGetSymbolAddress((void**)&xl,   g_xl);
    cudaGetSymbolAddress((void**)&wxh,  g_wxh);
    cudaGetSymbolAddress((void**)&wxl,  g_wxl);
    cudaGetSymbolAddress((void**)&whh,  g_whh);
    cudaGetSymbolAddress((void**)&whl,  g_whl);
    cudaGetSymbolAddress((void**)&hh,   g_hh);
    cudaGetSymbolAddress((void**)&hl,   g_hl);

    cudaFuncSetAttribute(fp16x3_gemm,
                         cudaFuncAttributeMaxDynamicSharedMemorySize, SMEM_BYTES);

    // serial prologue on the capture stream
    {
        int nx = T_ * B_ * NIN_;
        split_kernel<<<(nx + 255) / 256, 256>>>(x, xh, xl, nx);
        int nwx = NIN_ * G_;
        split_kernel<<<(nwx + 255) / 256, 256>>>(wx, wxh, wxl, nwx);
        int nwh = H_ * G_;
        split_kernel<<<(nwh + 255) / 256, 256>>>(wh, whh, whl, nwh);
    }

    fp16x3_gemm<<<dim3(G_ / GBN, (T_ * B_) / GBM, 1), 256, SMEM_BYTES>>>(
        xh, xl, wxh, wxl, Abuf, 0, G_, NIN_, NIN_);
    ln_rows_add_kernel<<<T_ * B_, 256>>>(Abuf, gx, bx, bvec, Abuf);
    init_state_kernel<<<(B_ * H_) / 256, 256>>>(init, mask);

    // fork two batch-half streams
    cudaStream_t s1, s2;
    cudaStreamCreateWithFlags(&s1, cudaStreamNonBlocking);
    cudaStreamCreateWithFlags(&s2, cudaStreamNonBlocking);
    cudaEvent_t ev0, ev1, ev2;
    cudaEventCreateWithFlags(&ev0, cudaEventDisableTiming);
    cudaEventCreateWithFlags(&ev1, cudaEventDisableTiming);
    cudaEventCreateWithFlags(&ev2, cudaEventDisableTiming);

    cudaEventRecord(ev0, 0);
    cudaStreamWaitEvent(s1, ev0, 0);
    cudaStreamWaitEvent(s2, ev0, 0);

    const int KCH = H_ / NSPLIT;
    const long long ZST = (long long)B_ * G_;

    for (int t = 0; t < T_; t++) {
        fp16x3_gemm<<<dim3(G_ / GBN, BHALF / GBM, NSPLIT), 256, SMEM_BYTES, s1>>>(
            hh, hl, whh, whl, HWp, ZST, G_, H_, KCH);
        cell_kernel<<<BHALF, 512, 0, s1>>>(t, 0, mask, Abuf, gh, bh, gc, bc, hs);
        fp16x3_gemm<<<dim3(G_ / GBN, BHALF / GBM, NSPLIT), 256, SMEM_BYTES, s2>>>(
            hh + (size_t)BHALF * H_, hl + (size_t)BHALF * H_, whh, whl,
            HWp + (size_t)BHALF * G_, ZST, G_, H_, KCH);
        cell_kernel<<<BHALF, 512, 0, s2>>>(t, BHALF, mask, Abuf, gh, bh, gc, bc, hs);
    }

    cudaEventRecord(ev1, s1);
    cudaEventRecord(ev2, s2);
    cudaStreamWaitEvent(0, ev1, 0);
    cudaStreamWaitEvent(0, ev2, 0);

    write_state_kernel<<<(B_ * H_) / 256, 256>>>(hs, sout);

    cudaEventDestroy(ev0);
    cudaEventDestroy(ev1);
    cudaEventDestroy(ev2);
    cudaStreamDestroy(s1);
    cudaStreamDestroy(s2);
}

// round 15
// speedup vs baseline: 1.1202x; 1.0635x over previous
#include <cuda_runtime.h>
#include <cuda_pipeline.h>
#include <cuda_fp16.h>
#include <mma.h>
#include <math.h>

using namespace nvcuda;

#define T_   64
#define B_   256
#define NIN_ 1024
#define H_   2048
#define G_   8192   // 4*H
#define NSPLIT 2
#define BHALF 128   // batch rows per stream

// ---- scratch ----
__device__ float g_P[(size_t)T_ * B_ * G_];          // raw x@wx (pre-LN)
__device__ float g_HWp[(size_t)NSPLIT * B_ * G_];    // split-K partials of h@wh
__device__ float g_c[(size_t)B_ * H_];
__device__ __half g_hh[(size_t)B_ * H_];
__device__ __half g_hl[(size_t)B_ * H_];
__device__ __half g_xh[(size_t)T_ * B_ * NIN_];
__device__ __half g_xl[(size_t)T_ * B_ * NIN_];
__device__ __half g_wxh[(size_t)NIN_ * G_];
__device__ __half g_wxl[(size_t)NIN_ * G_];
__device__ __half g_whh[(size_t)H_ * G_];
__device__ __half g_whl[(size_t)H_ * G_];

// ============================================================
// Fused fp16x3 GEMM: one launch covers recurrent split-K halves
// (z=0,1: 128-row h-half @ wh chunk) AND the xw slice for this
// (t, half) (z=2: 128 x-rows @ wx). All roles: K=1024, N=G_.
// Block 128x128, 8 warps (4x2), warp tile 32x64, BK=32,
// 3-stage cp.async, one __syncthreads per k-iter.
// ============================================================
#define GBM 128
#define GBN 128
#define GBK 32
#define ALD 40
#define BLD 136
#define NSTAGE 3
#define AS_H (GBM * ALD)
#define BS_H (GBK * BLD)
#define STAGE_H (2 * AS_H + 2 * BS_H)
#define SMEM_BYTES (STAGE_H * NSTAGE * 2)
#define KCH 1024
#define NIT (KCH / GBK)   // 32

__global__ __launch_bounds__(256, 2) void fused_gemm(
    const __half* __restrict__ Arec_h, const __half* __restrict__ Arec_l,
    const __half* __restrict__ Brec_h, const __half* __restrict__ Brec_l,
    const __half* __restrict__ Axw_h,  const __half* __restrict__ Axw_l,
    const __half* __restrict__ Bxw_h,  const __half* __restrict__ Bxw_l,
    float* __restrict__ Crec, long long zstride,
    float* __restrict__ Cxw)
{
    extern __shared__ __half smem[];

    const int tid = threadIdx.x;
    const int z = blockIdx.z;

    const __half *Ah_, *Al_, *Bh_, *Bl_;
    float* Cc;
    int arsk;   // A row stride
    if (z == 2) {
        Ah_ = Axw_h;  Al_ = Axw_l;
        Bh_ = Bxw_h;  Bl_ = Bxw_l;
        Cc = Cxw;     arsk = NIN_;
    } else {
        Ah_ = Arec_h + z * KCH;
        Al_ = Arec_l + z * KCH;
        Bh_ = Brec_h + (size_t)z * KCH * G_;
        Bl_ = Brec_l + (size_t)z * KCH * G_;
        Cc = Crec + (size_t)z * zstride;
        arsk = H_;
    }

    const __half* Abh = Ah_;
    const __half* Abl = Al_;
    const __half* Bbh = Bh_ + (size_t)blockIdx.x * GBN;
    const __half* Bbl = Bl_ + (size_t)blockIdx.x * GBN;

    const int warp = tid >> 5;
    const int wm = warp & 3;
    const int wn = warp >> 2;

    wmma::fragment<wmma::accumulator, 16, 16, 16, float> acc[2][4];
    #pragma unroll
    for (int i = 0; i < 2; i++)
        #pragma unroll
        for (int j = 0; j < 4; j++)
            wmma::fill_fragment(acc[i][j], 0.0f);

    auto prefetch = [&](int it) {
        __half* s = smem + (size_t)(it % NSTAGE) * STAGE_H;
        __half* sAh = s;
        __half* sAl = s + AS_H;
        __half* sBh = s + 2 * AS_H;
        __half* sBl = s + 2 * AS_H + BS_H;
        const int k0 = it * GBK;
        #pragma unroll
        for (int q = 0; q < 2; q++) {
            int sa = tid * 2 + q;
            int r = sa >> 2, c = (sa & 3) * 8;
            __pipeline_memcpy_async(&sAh[r * ALD + c], Abh + (size_t)r * arsk + k0 + c, 16);
            __pipeline_memcpy_async(&sAl[r * ALD + c], Abl + (size_t)r * arsk + k0 + c, 16);
            int rb = sa >> 4, cb = (sa & 15) * 8;
            __pipeline_memcpy_async(&sBh[rb * BLD + cb], Bbh + (size_t)(k0 + rb) * G_ + cb, 16);
            __pipeline_memcpy_async(&sBl[rb * BLD + cb], Bbl + (size_t)(k0 + rb) * G_ + cb, 16);
        }
    };

    prefetch(0); __pipeline_commit();
    prefetch(1); __pipeline_commit();

    for (int it = 0; it < NIT; ++it) {
        __pipeline_wait_prior((it + 1 < NIT) ? 1 : 0);
        __syncthreads();

        if (it + 2 < NIT) { prefetch(it + 2); __pipeline_commit(); }

        const __half* s = smem + (size_t)(it % NSTAGE) * STAGE_H;
        const __half* sAh = s;
        const __half* sAl = s + AS_H;
        const __half* sBh = s + 2 * AS_H;
        const __half* sBl = s + 2 * AS_H + BS_H;

        #pragma unroll
        for (int ks = 0; ks < GBK; ks += 16) {
            wmma::fragment<wmma::matrix_a, 16, 16, 16, __half, wmma::row_major> ah[2], al[2];
            #pragma unroll
            for (int i = 0; i < 2; i++) {
                wmma::load_matrix_sync(ah[i], &sAh[(wm * 32 + i * 16) * ALD + ks], ALD);
                wmma::load_matrix_sync(al[i], &sAl[(wm * 32 + i * 16) * ALD + ks], ALD);
            }
            #pragma unroll
            for (int j = 0; j < 4; j++) {
                const int colb = wn * 64 + j * 16;
                wmma::fragment<wmma::matrix_b, 16, 16, 16, __half, wmma::row_major> bf;
                wmma::load_matrix_sync(bf, &sBh[ks * BLD + colb], BLD);
                wmma::mma_sync(acc[0][j], al[0], bf, acc[0][j]);
                wmma::mma_sync(acc[1][j], al[1], bf, acc[1][j]);
                wmma::mma_sync(acc[0][j], ah[0], bf, acc[0][j]);
                wmma::mma_sync(acc[1][j], ah[1], bf, acc[1][j]);
                wmma::load_matrix_sync(bf, &sBl[ks * BLD + colb], BLD);
                wmma::mma_sync(acc[0][j], ah[0], bf, acc[0][j]);
                wmma::mma_sync(acc[1][j], ah[1], bf, acc[1][j]);
            }
        }
    }

    float* Cb = Cc + (size_t)(wm * 32) * G_
                   + (size_t)blockIdx.x * GBN + wn * 64;
    #pragma unroll
    for (int i = 0; i < 2; i++)
        #pragma unroll
        for (int j = 0; j < 4; j++)
            wmma::store_matrix_sync(Cb + (size_t)(i * 16) * G_ + j * 16,
                                    acc[i][j], G_, wmma::mem_row_major);
}

// ============================================================
__device__ __forceinline__ float fsigmoid(float x)
{
    return __fdividef(1.f, 1.f + __expf(-x));
}
__device__ __forceinline__ float ftanh(float x)
{
    return __fdividef(2.f, 1.f + __expf(-2.f * x)) - 1.f;
}

__global__ void split_kernel(const float* __restrict__ in,
                             __half* __restrict__ hi, __half* __restrict__ lo,
                             int n)
{
    int i = blockIdx.x * blockDim.x + threadIdx.x;
    if (i < n) {
        float v = in[i];
        __half h = __float2half_rn(v);
        hi[i] = h;
        lo[i] = __float2half_rn(v - __half2float(h));
    }
}

__device__ __forceinline__ void blk_reduce2_512(float& s, float& s2)
{
    __shared__ float rbuf[2][16];
    const int lane = threadIdx.x & 31;
    const int warp = threadIdx.x >> 5;
    #pragma unroll
    for (int o = 16; o; o >>= 1) {
        s  += __shfl_down_sync(0xffffffffu, s,  o);
        s2 += __shfl_down_sync(0xffffffffu, s2, o);
    }
    if (lane == 0) { rbuf[0][warp] = s; rbuf[1][warp] = s2; }
    __syncthreads();
    if (warp == 0) {
        s  = (lane < 16) ? rbuf[0][lane] : 0.f;
        s2 = (lane < 16) ? rbuf[1][lane] : 0.f;
        #pragma unroll
        for (int o = 8; o; o >>= 1) {
            s  += __shfl_down_sync(0xffffffffu, s,  o);
            s2 += __shfl_down_sync(0xffffffffu, s2, o);
        }
        if (lane == 0) { rbuf[0][0] = s; rbuf[1][0] = s2; }
    }
    __syncthreads();
    s  = rbuf[0][0];
    s2 = rbuf[1][0];
    __syncthreads();
}

__global__ void init_state_kernel(const float* __restrict__ init,
                                  const float* __restrict__ mask)
{
    int idx = blockIdx.x * blockDim.x + threadIdx.x;
    int b = idx >> 11;
    int j = idx & (H_ - 1);
    size_t base = (size_t)b * T_ * 2 * H_;
    g_c[idx] = init[base + j];
    float h = init[base + H_ + j] * (1.f - mask[b]);
    __half hh = __float2half_rn(h);
    g_hh[idx] = hh;
    g_hl[idx] = __float2half_rn(h - __half2float(hh));
}

// ============================================================
// Fused cell: computes BOTH layernorms (raw P row and hw row),
// gates, c/h update. One batch half per launch (128 blocks).
// ============================================================
__global__ __launch_bounds__(512) void cell_kernel(
    int t, int b0, const float* __restrict__ mask,
    const float* __restrict__ P,
    const float* __restrict__ gx, const float* __restrict__ bx,
    const float* __restrict__ bvec,
    const float* __restrict__ gh, const float* __restrict__ bh,
    const float* __restrict__ gc, const float* __restrict__ bc,
    float* __restrict__ hs)
{
    const int b = blockIdx.x + b0;
    const int tid = threadIdx.x;
    const float keep = 1.f - mask[t * B_ + b];
    const float keep_next = (t + 1 < T_) ? (1.f - mask[(t + 1) * B_ + b]) : 1.f;
    const float* hw0 = g_HWp + (size_t)b * G_;
    const size_t PS = (size_t)B_ * G_;
    const float* p = P + ((size_t)t * B_ + b) * G_;

    // pass 1: joint stats of hw row and P row
    float sH = 0.f, s2H = 0.f, sP = 0.f, s2P = 0.f;
    #pragma unroll
    for (int pp = 0; pp < G_ / (512 * 4); pp++) {
        int i4 = (tid + pp * 512) * 4;
        float4 a0 = *(const float4*)(hw0 + i4);
        float4 a1 = *(const float4*)(hw0 + PS + i4);
        float4 pv = *(const float4*)(p + i4);
        float v0 = a0.x + a1.x, v1 = a0.y + a1.y;
        float v2 = a0.z + a1.z, v3 = a0.w + a1.w;
        sH  += v0 + v1 + v2 + v3;
        s2H += v0 * v0 + v1 * v1 + v2 * v2 + v3 * v3;
        sP  += pv.x + pv.y + pv.z + pv.w;
        s2P += pv.x * pv.x + pv.y * pv.y + pv.z * pv.z + pv.w * pv.w;
    }
    blk_reduce2_512(sH, s2H);
    blk_reduce2_512(sP, s2P);
    const float invG = 1.f / (float)G_;
    float muH   = sH * invG;
    float rstdH = rsqrtf(s2H * invG - muH * muH + 1e-5f);
    float muP   = sP * invG;
    float rstdP = rsqrtf(s2P * invG - muP * muP + 1e-5f);

    const int j0 = tid * 4;
    float cs = 0.f, cs2 = 0.f;
    float cn4[4], og4[4];
    {
        float z4[4][4];   // [gate][lane4]
        #pragma unroll
        for (int g = 0; g < 4; g++) {
            const size_t o = (size_t)g * H_ + j0;
            float4 hw = *(const float4*)(hw0 + o);
            float4 q  = *(const float4*)(hw0 + PS + o);
            hw.x += q.x; hw.y += q.y; hw.z += q.z; hw.w += q.w;
            float4 pv  = *(const float4*)(p + o);
            float4 gx4 = *(const float4*)(gx + o);
            float4 bx4 = *(const float4*)(bx + o);
            float4 bb4 = *(const float4*)(bvec + o);
            float4 gh4 = *(const float4*)(gh + o);
            float4 bh4 = *(const float4*)(bh + o);
            z4[g][0] = (pv.x - muP) * rstdP * gx4.x + bx4.x + bb4.x + (hw.x - muH) * rstdH * gh4.x + bh4.x;
            z4[g][1] = (pv.y - muP) * rstdP * gx4.y + bx4.y + bb4.y + (hw.y - muH) * rstdH * gh4.y + bh4.y;
            z4[g][2] = (pv.z - muP) * rstdP * gx4.z + bx4.z + bb4.z + (hw.z - muH) * rstdH * gh4.z + bh4.z;
            z4[g][3] = (pv.w - muP) * rstdP * gx4.w + bx4.w + bb4.w + (hw.w - muH) * rstdH * gh4.w + bh4.w;
        }
        float4 cc = *(const float4*)(&g_c[(size_t)b * H_ + j0]);
        float cc_[4] = {cc.x, cc.y, cc.z, cc.w};
        #pragma unroll
        for (int q4 = 0; q4 < 4; q4++) {
            float ig = fsigmoid(z4[0][q4]);
            float fg = fsigmoid(z4[1][q4]);
            float og = fsigmoid(z4[2][q4]);
            float ug = ftanh(z4[3][q4]);
            float cn = fg * (cc_[q4] * keep) + ig * ug;
            cn4[q4] = cn;
            og4[q4] = og;
            cs += cn; cs2 += cn * cn;
        }
        *(float4*)(&g_c[(size_t)b * H_ + j0]) =
            make_float4(cn4[0], cn4[1], cn4[2], cn4[3]);
    }
    blk_reduce2_512(cs, cs2);
    const float invH = 1.f / (float)H_;
    float muc   = cs * invH;
    float rstdc = rsqrtf(cs2 * invH - muc * muc + 1e-5f);

    {
        float4 gc4 = *(const float4*)(gc + j0);
        float4 bc4 = *(const float4*)(bc + j0);
        float gc_[4] = {gc4.x, gc4.y, gc4.z, gc4.w};
        float bc_[4] = {bc4.x, bc4.y, bc4.z, bc4.w};
        float hn[4];
        __half hhp[4], hlp[4];
        #pragma unroll
        for (int q4 = 0; q4 < 4; q4++) {
            float v = og4[q4] * ftanh((cn4[q4] - muc) * rstdc * gc_[q4] + bc_[q4]);
            hn[q4] = v;
            float hm = v * keep_next;
            __half hhi = __float2half_rn(hm);
            hhp[q4] = hhi;
            hlp[q4] = __float2half_rn(hm - __half2float(hhi));
        }
        *(float4*)(hs + ((size_t)t * B_ + b) * H_ + j0) =
            make_float4(hn[0], hn[1], hn[2], hn[3]);
        __half2* ph = (__half2*)(&g_hh[(size_t)b * H_ + j0]);
        ph[0] = __halves2half2(hhp[0], hhp[1]);
        ph[1] = __halves2half2(hhp[2], hhp[3]);
        __half2* pl = (__half2*)(&g_hl[(size_t)b * H_ + j0]);
        pl[0] = __halves2half2(hlp[0], hlp[1]);
        pl[1] = __halves2half2(hlp[2], hlp[3]);
    }
}

__global__ void write_state_kernel(const float* __restrict__ hs,
                                   float* __restrict__ sout)
{
    int idx = blockIdx.x * blockDim.x + threadIdx.x;
    int b = idx >> 11;
    int j = idx & (H_ - 1);
    sout[(size_t)b * 2 * H_ + j] = g_c[idx];
    sout[(size_t)b * 2 * H_ + H_ + j] =
        hs[((size_t)(T_ - 1) * B_ + b) * H_ + j];
}

// ============================================================
extern "C" void kernel_launch(void* const* d_in, const int* in_sizes, int n_in,
                              void* d_out, int out_size)
{
    const float* x    = (const float*)d_in[0];
    const float* mask = (const float*)d_in[1];
    const float* init = (const float*)d_in[2];
    const float* wx   = (const float*)d_in[3];
    const float* wh   = (const float*)d_in[4];
    const float* bvec = (const float*)d_in[5];
    const float* gx   = (const float*)d_in[6];
    const float* bx   = (const float*)d_in[7];
    const float* gh   = (const float*)d_in[8];
    const float* bh   = (const float*)d_in[9];
    const float* gc   = (const float*)d_in[10];
    const float* bc   = (const float*)d_in[11];

    float* out  = (float*)d_out;
    float* hs   = out;
    float* sout = out + (size_t)T_ * B_ * H_;

    float *Pbuf, *HWp;
    __half *xh, *xl, *wxh, *wxl, *whh, *whl, *hh, *hl;
    cudaGetSymbolAddress((void**)&Pbuf, g_P);
    cudaGetSymbolAddress((void**)&HWp,  g_HWp);
    cudaGetSymbolAddress((void**)&xh,   g_xh);
    cudaGetSymbolAddress((void**)&xl,   g_xl);
    cudaGetSymbolAddress((void**)&wxh,  g_wxh);
    cudaGetSymbolAddress((void**)&wxl,  g_wxl);
    cudaGetSymbolAddress((void**)&whh,  g_whh);
    cudaGetSymbolAddress((void**)&whl,  g_whl);
    cudaGetSymbolAddress((void**)&hh,   g_hh);
    cudaGetSymbolAddress((void**)&hl,   g_hl);

    cudaFuncSetAttribute(fused_gemm,
                         cudaFuncAttributeMaxDynamicSharedMemorySize, SMEM_BYTES);

    // prologue: splits + state init only
    {
        int nx = T_ * B_ * NIN_;
        split_kernel<<<(nx + 255) / 256, 256>>>(x, xh, xl, nx);
        int nwx = NIN_ * G_;
        split_kernel<<<(nwx + 255) / 256, 256>>>(wx, wxh, wxl, nwx);
        int nwh = H_ * G_;
        split_kernel<<<(nwh + 255) / 256, 256>>>(wh, whh, whl, nwh);
    }
    init_state_kernel<<<(B_ * H_) / 256, 256>>>(init, mask);

    cudaStream_t s1, s2;
    cudaStreamCreateWithFlags(&s1, cudaStreamNonBlocking);
    cudaStreamCreateWithFlags(&s2, cudaStreamNonBlocking);
    cudaEvent_t ev0, ev1, ev2;
    cudaEventCreateWithFlags(&ev0, cudaEventDisableTiming);
    cudaEventCreateWithFlags(&ev1, cudaEventDisableTiming);
    cudaEventCreateWithFlags(&ev2, cudaEventDisableTiming);

    cudaEventRecord(ev0, 0);
    cudaStreamWaitEvent(s1, ev0, 0);
    cudaStreamWaitEvent(s2, ev0, 0);

    const long long ZST = (long long)B_ * G_;

    for (int t = 0; t < T_; t++) {
        // half A (rows 0..127)
        {
            const size_t xo = ((size_t)t * B_ + 0) * NIN_;
            float* Po = Pbuf + ((size_t)t * B_ + 0) * G_;
            fused_gemm<<<dim3(G_ / GBN, 1, 3), 256, SMEM_BYTES, s1>>>(
                hh, hl, whh, whl,
                xh + xo, xl + xo, wxh, wxl,
                HWp, ZST, Po);
            cell_kernel<<<BHALF, 512, 0, s1>>>(
                t, 0, mask, Pbuf, gx, bx, bvec, gh, bh, gc, bc, hs);
        }
        // half B (rows 128..255)
        {
            const size_t xo = ((size_t)t * B_ + BHALF) * NIN_;
            float* Po = Pbuf + ((size_t)t * B_ + BHALF) * G_;
            fused_gemm<<<dim3(G_ / GBN, 1, 3), 256, SMEM_BYTES, s2>>>(
                hh + (size_t)BHALF * H_, hl + (size_t)BHALF * H_, whh, whl,
                xh + xo, xl + xo, wxh, wxl,
                HWp + (size_t)BHALF * G_, ZST, Po);
            cell_kernel<<<BHALF, 512, 0, s2>>>(
                t, BHALF, mask, Pbuf, gx, bx, bvec, gh, bh, gc, bc, hs);
        }
    }

    cudaEventRecord(ev1, s1);
    cudaEventRecord(ev2, s2);
    cudaStreamWaitEvent(0, ev1, 0);
    cudaStreamWaitEvent(0, ev2, 0);

    write_state_kernel<<<(B_ * H_) / 256, 256>>>(hs, sout);

    cudaEventDestroy(ev0);
    cudaEventDestroy(ev1);
    cudaEventDestroy(ev2);
    cudaStreamDestroy(s1);
    cudaStreamDestroy(s2);
}